// round 15
// baseline (speedup 1.0000x reference)
#include <cuda_runtime.h>
#include <cuda_bf16.h>
#include <math.h>
#include <stdint.h>

// Problem constants (fixed shapes)
#define BB   4
#define LL   2048
#define DD   256
#define DIN  512
#define NSS  16
#define DTR_ 16
#define DFF_ 1024
#define TOK  (BB*LL)      // 8192
#define NCH  (BB*DIN)     // 2048 scan channels
#define GCH  16           // scan chunks
#define CL   (LL/GCH)     // 128 steps per chunk

// ---------------- scratch (static device memory) ----------------
__device__ float          g_xz    [TOK * 2 * DIN];
__device__ float          g_xcT   [TOK * DIN];
__device__ float          g_zsT   [TOK * DIN];
__device__ __nv_bfloat16  g_xconvb[TOK * DIN];
__device__ float          g_xdbl  [TOK * 64];
__device__ float          g_dtT   [TOK * DIN];
__device__ float          g_P     [NCH * GCH * NSS];
__device__ float          g_He    [NCH * GCH * NSS];
__device__ __nv_bfloat16  g_ygb   [TOK * DIN];
__device__ float          g_ssm   [TOK * DD];
__device__ float          g_y1    [TOK * DD];
__device__ __nv_bfloat16  g_y1b   [TOK * DD];
__device__ __nv_bfloat16  g_h1b   [TOK * DFF_];
__device__ float          g_f2    [TOK * DD];
__device__ __nv_bfloat16  g_xb    [TOK * DD];
__device__ __nv_bfloat16  g_w_in  [2 * DIN * DD];
__device__ __nv_bfloat16  g_w_xp  [64 * DIN];
__device__ __nv_bfloat16  g_w_out [DD * DIN];
__device__ __nv_bfloat16  g_w_fc1 [DFF_ * DD];
__device__ __nv_bfloat16  g_w_fc2 [DD * DFF_];
__device__ float          g_zero  [64];

// ---------------- math helpers ----------------
__device__ __forceinline__ float siluf(float v)     { return v / (1.f + __expf(-v)); }
__device__ __forceinline__ float geluf(float v)     { return 0.5f * v * (1.f + erff(v * 0.70710678118654752f)); }
__device__ __forceinline__ float softplusf(float v) { return fmaxf(v, 0.f) + log1pf(__expf(-fabsf(v))); }

__device__ __forceinline__ uint32_t smem_u32(const void* p) {
    uint32_t a;
    asm("{ .reg .u64 t; cvta.to.shared.u64 t, %1; cvt.u32.u64 %0, t; }" : "=r"(a) : "l"(p));
    return a;
}
__device__ __forceinline__ void ldsm4(uint32_t& r0, uint32_t& r1, uint32_t& r2, uint32_t& r3, uint32_t addr) {
    asm volatile("ldmatrix.sync.aligned.m8n8.x4.shared.b16 {%0,%1,%2,%3}, [%4];"
                 : "=r"(r0), "=r"(r1), "=r"(r2), "=r"(r3) : "r"(addr));
}
__device__ __forceinline__ void mma16816(float* c, const uint32_t* a, const uint32_t* b) {
    asm volatile("mma.sync.aligned.m16n8k16.row.col.f32.bf16.bf16.f32 "
                 "{%0,%1,%2,%3},{%4,%5,%6,%7},{%8,%9},{%0,%1,%2,%3};"
                 : "+f"(c[0]), "+f"(c[1]), "+f"(c[2]), "+f"(c[3])
                 : "r"(a[0]), "r"(a[1]), "r"(a[2]), "r"(a[3]), "r"(b[0]), "r"(b[1]));
}
__device__ __forceinline__ void cp16(uint32_t dst, const void* src) {
    asm volatile("cp.async.cg.shared.global [%0], [%1], 16;" :: "r"(dst), "l"(src));
}
#define CP_COMMIT() asm volatile("cp.async.commit_group;" ::: "memory")

// =======================================================================
// bf16 GEMM, BM templated (128 or 64). BK=64, 3-stage cp.async, one
// __syncthreads per iteration. 256 threads = 2(M) x 4(N) warps.
// =======================================================================
template<int BMt, int BN, int EPI, int OUTT>
__global__ __launch_bounds__(256)
void mma_gemm(const __nv_bfloat16* __restrict__ A, const __nv_bfloat16* __restrict__ W,
              const float* __restrict__ bias, void* __restrict__ C, int N, int K)
{
    constexpr int BK  = 64;
    constexpr int AST = 72;
    constexpr int MI  = BMt / 32;
    constexpr int NT  = BN / 32;
    constexpr int ASZ = BMt * AST;
    constexpr int BSZ = BN * AST;

    extern __shared__ __nv_bfloat16 smem[];
    __nv_bfloat16* sA = smem;
    __nv_bfloat16* sB = smem + 3 * ASZ;

    const int tid  = threadIdx.x;
    const int wid  = tid >> 5;
    const int lane = tid & 31;
    const int warp_m = wid & 1;
    const int warp_n = wid >> 1;
    const int rowBase = blockIdx.y * BMt;
    const int colBase = blockIdx.x * BN;
    const int NK = K >> 6;

    auto prefetch = [&](int s, int kc) {
        __nv_bfloat16* As = sA + s * ASZ;
        __nv_bfloat16* Bs = sB + s * BSZ;
        #pragma unroll
        for (int i = 0; i < BMt / 32; i++) {
            const int cidx = i * 256 + tid;
            const int row = cidx >> 3, c8 = cidx & 7;
            cp16(smem_u32(&As[row * AST + c8 * 8]),
                 A + (size_t)(rowBase + row) * K + kc * BK + c8 * 8);
        }
        #pragma unroll
        for (int i = 0; i < BN / 32; i++) {
            const int cidx = i * 256 + tid;
            const int row = cidx >> 3, c8 = cidx & 7;
            cp16(smem_u32(&Bs[row * AST + c8 * 8]),
                 W + (size_t)(colBase + row) * K + kc * BK + c8 * 8);
        }
    };

    float acc[MI][NT][4];
    #pragma unroll
    for (int mi = 0; mi < MI; mi++)
        #pragma unroll
        for (int ni = 0; ni < NT; ni++)
            #pragma unroll
            for (int r = 0; r < 4; r++) acc[mi][ni][r] = 0.f;

    prefetch(0, 0); CP_COMMIT();
    prefetch(1, 1); CP_COMMIT();

    for (int kt = 0; kt < NK; kt++) {
        if (kt + 1 < NK) asm volatile("cp.async.wait_group 1;" ::: "memory");
        else             asm volatile("cp.async.wait_group 0;" ::: "memory");
        __syncthreads();
        if (kt + 2 < NK) { prefetch((kt + 2) % 3, kt + 2); CP_COMMIT(); }

        const int s = kt % 3;
        __nv_bfloat16* As = sA + s * ASZ;
        __nv_bfloat16* Bs = sB + s * BSZ;
        #pragma unroll
        for (int k = 0; k < 4; k++) {
            uint32_t af[MI][4];
            #pragma unroll
            for (int mi = 0; mi < MI; mi++) {
                const int row = warp_m * (MI * 16) + mi * 16 + (lane & 15);
                const int col = k * 16 + (lane >> 4) * 8;
                ldsm4(af[mi][0], af[mi][1], af[mi][2], af[mi][3],
                      smem_u32(&As[row * AST + col]));
            }
            uint32_t bf[NT][2];
            #pragma unroll
            for (int np = 0; np < NT / 2; np++) {
                const int n0 = warp_n * (NT * 8) + np * 16;
                const int q  = lane >> 3;
                const int row = n0 + (q & 1) * 8 + (lane & 7);
                const int col = k * 16 + (q >> 1) * 8;
                uint32_t r0, r1, r2, r3;
                ldsm4(r0, r1, r2, r3, smem_u32(&Bs[row * AST + col]));
                bf[np*2][0] = r0; bf[np*2+1][0] = r1;
                bf[np*2][1] = r2; bf[np*2+1][1] = r3;
            }
            #pragma unroll
            for (int mi = 0; mi < MI; mi++)
                #pragma unroll
                for (int ni = 0; ni < NT; ni++)
                    mma16816(acc[mi][ni], af[mi], bf[ni]);
        }
    }
    __syncthreads();

    const int g  = lane >> 2;
    const int c2 = (lane & 3) * 2;
    #pragma unroll
    for (int mi = 0; mi < MI; mi++) {
        const int row0 = rowBase + warp_m * (MI * 16) + mi * 16 + g;
        #pragma unroll
        for (int ni = 0; ni < NT; ni++) {
            const int col = colBase + warp_n * (NT * 8) + ni * 8 + c2;
            const float b0 = bias[col], b1 = bias[col + 1];
            float v00 = acc[mi][ni][0] + b0, v01 = acc[mi][ni][1] + b1;
            float v10 = acc[mi][ni][2] + b0, v11 = acc[mi][ni][3] + b1;
            if (EPI == 1) { v00 = geluf(v00); v01 = geluf(v01); v10 = geluf(v10); v11 = geluf(v11); }
            if (OUTT == 0) {
                *(float2*)((float*)C + (size_t)row0 * N + col)       = make_float2(v00, v01);
                *(float2*)((float*)C + (size_t)(row0 + 8) * N + col) = make_float2(v10, v11);
            } else {
                __nv_bfloat16* Cb = (__nv_bfloat16*)C;
                *(__nv_bfloat162*)(Cb + (size_t)row0 * N + col)       = __float22bfloat162_rn(make_float2(v00, v01));
                *(__nv_bfloat162*)(Cb + (size_t)(row0 + 8) * N + col) = __float22bfloat162_rn(make_float2(v10, v11));
            }
        }
    }
}

// ---------------- single fused converter ----------------
#define CV0 (TOK*DD)
#define CV1 (2*DIN*DD)
#define CV2 (DD*DIN)
#define CV3 (DFF_*DD)
#define CV4 (DD*DFF_)
#define CV5 (64*DIN)
__global__ void cvt_all_kernel(const float* __restrict__ x,        __nv_bfloat16* __restrict__ xb,
                               const float* __restrict__ w_in,     __nv_bfloat16* __restrict__ ob_in,
                               const float* __restrict__ w_out,    __nv_bfloat16* __restrict__ ob_out,
                               const float* __restrict__ w_fc1,    __nv_bfloat16* __restrict__ ob_fc1,
                               const float* __restrict__ w_fc2,    __nv_bfloat16* __restrict__ ob_fc2,
                               const float* __restrict__ w_xp,     __nv_bfloat16* __restrict__ ob_xp)
{
    int i = blockIdx.x * blockDim.x + threadIdx.x;
    if (i < CV0) { xb[i]     = __float2bfloat16(x[i]);     return; }  i -= CV0;
    if (i < CV1) { ob_in[i]  = __float2bfloat16(w_in[i]);  return; }  i -= CV1;
    if (i < CV2) { ob_out[i] = __float2bfloat16(w_out[i]); return; }  i -= CV2;
    if (i < CV3) { ob_fc1[i] = __float2bfloat16(w_fc1[i]); return; }  i -= CV3;
    if (i < CV4) { ob_fc2[i] = __float2bfloat16(w_fc2[i]); return; }  i -= CV4;
    if (i < CV5) {
        const int r = i >> 9, k = i & 511;
        ob_xp[i] = __float2bfloat16(r < 48 ? w_xp[r * 512 + k] : 0.f);
    }
}

// ---------------- SIMT SGEMM for dt_proj (K=16) -> dtT channel-major ----------------
__global__ __launch_bounds__(256)
void gemm_kernel_sp(const float* __restrict__ A, int lda,
                    const float* __restrict__ W, const float* __restrict__ bias,
                    float* __restrict__ dtT, int N, int K)
{
    __shared__ float As[16][132];
    __shared__ float Bs[16][132];
    const int tid = threadIdx.x;
    const int tx = tid & 15, ty = tid >> 4;
    const int rowBase = blockIdx.y * 128, colBase = blockIdx.x * 128;
    const int r = tid >> 2, c4 = tid & 3;
    float acc[8][8];
    #pragma unroll
    for (int i = 0; i < 8; i++) {
        #pragma unroll
        for (int j = 0; j < 8; j++) acc[i][j] = 0.f;
    }
    for (int kt = 0; kt < K; kt += 16) {
        #pragma unroll
        for (int rr = r; rr < 128; rr += 64) {
            float4 va = *reinterpret_cast<const float4*>(&A[(size_t)(rowBase + rr) * lda + kt + c4 * 4]);
            As[c4*4+0][rr] = va.x; As[c4*4+1][rr] = va.y; As[c4*4+2][rr] = va.z; As[c4*4+3][rr] = va.w;
            float4 vb = *reinterpret_cast<const float4*>(&W[(size_t)(colBase + rr) * K + kt + c4 * 4]);
            Bs[c4*4+0][rr] = vb.x; Bs[c4*4+1][rr] = vb.y; Bs[c4*4+2][rr] = vb.z; Bs[c4*4+3][rr] = vb.w;
        }
        __syncthreads();
        #pragma unroll
        for (int k = 0; k < 16; k++) {
            float a8[8], b8[8];
            #pragma unroll
            for (int i = 0; i < 8; i++) a8[i] = As[k][ty * 8 + i];
            #pragma unroll
            for (int j = 0; j < 8; j++) b8[j] = Bs[k][tx * 8 + j];
            #pragma unroll
            for (int i = 0; i < 8; i++)
                #pragma unroll
                for (int j = 0; j < 8; j++) acc[i][j] = fmaf(a8[i], b8[j], acc[i][j]);
        }
        __syncthreads();
    }
    const int t0 = rowBase + ty * 8;
    const int b  = t0 >> 11;
    const int l  = t0 & 2047;
    #pragma unroll
    for (int j = 0; j < 8; j++) {
        const int col = colBase + tx * 8 + j;
        const float bj = bias[col];
        float v[8];
        #pragma unroll
        for (int i = 0; i < 8; i++) v[i] = softplusf(acc[i][j] + bj);
        float* o = dtT + ((size_t)(b * DIN + col)) * LL + l;
        *(float4*)(o)     = make_float4(v[0], v[1], v[2], v[3]);
        *(float4*)(o + 4) = make_float4(v[4], v[5], v[6], v[7]);
    }
}

// ---------------- conv+silu with transpose: 64-channel tiles, float4 IO ----------------
__global__ __launch_bounds__(256)
void conv_silu_tr(const float* __restrict__ xz, const float* __restrict__ cw,
                  const float* __restrict__ cb, __nv_bfloat16* __restrict__ xconvb,
                  float* __restrict__ xcT, float* __restrict__ zsT)
{
    __shared__ float sxi[35][65];
    __shared__ float sout[32][65];
    __shared__ float sz[32][65];
    const int l0 = blockIdx.x * 32;
    const int d0 = blockIdx.y * 64;
    const int b  = blockIdx.z;
    const int tid = threadIdx.x;

    #pragma unroll 2
    for (int i = tid; i < 35 * 16; i += 256) {
        const int r = i >> 4, c4 = (i & 15) * 4;
        const int l = l0 - 3 + r;
        float4 v = make_float4(0.f, 0.f, 0.f, 0.f);
        if (l >= 0) v = *(const float4*)&xz[((size_t)(b * LL + l)) * (2 * DIN) + d0 + c4];
        sxi[r][c4+0] = v.x; sxi[r][c4+1] = v.y; sxi[r][c4+2] = v.z; sxi[r][c4+3] = v.w;
    }
    #pragma unroll 2
    for (int i = tid; i < 32 * 16; i += 256) {
        const int r = i >> 4, c4 = (i & 15) * 4;
        float4 v = *(const float4*)&xz[((size_t)(b * LL + l0 + r)) * (2 * DIN) + DIN + d0 + c4];
        sz[r][c4+0] = v.x; sz[r][c4+1] = v.y; sz[r][c4+2] = v.z; sz[r][c4+3] = v.w;
    }
    __syncthreads();
    #pragma unroll 4
    for (int i = tid; i < 32 * 64; i += 256) {
        const int l = i >> 6, c = i & 63;
        const int d = d0 + c;
        float v = cb[d] + cw[d*4+3] * sxi[l+3][c] + cw[d*4+2] * sxi[l+2][c]
                        + cw[d*4+1] * sxi[l+1][c] + cw[d*4+0] * sxi[l][c];
        v = siluf(v);
        sout[l][c] = v;
        xconvb[((size_t)(b * LL + l0 + l)) * DIN + d] = __float2bfloat16(v);
    }
    __syncthreads();
    #pragma unroll 2
    for (int i = tid; i < 64 * 8; i += 256) {
        const int c = i >> 3, lg = (i & 7) * 4;
        const size_t o = ((size_t)(b * DIN + d0 + c)) * LL + l0 + lg;
        *(float4*)&xcT[o] = make_float4(sout[lg][c], sout[lg+1][c], sout[lg+2][c], sout[lg+3][c]);
        *(float4*)&zsT[o] = make_float4(siluf(sz[lg][c]), siluf(sz[lg+1][c]),
                                        siluf(sz[lg+2][c]), siluf(sz[lg+3][c]));
    }
}

// ---------------- chunked parallel scan (float4-batched broadcast loads) ----------------
__global__ __launch_bounds__(256)
void scan_p1(const float* __restrict__ dtT, const float* __restrict__ xdbl,
             const float* __restrict__ xcT, const float* __restrict__ A_log,
             float* __restrict__ Pst, float* __restrict__ He)
{
    __shared__ __align__(16) float bufB[2][64][16];
    const int tid = threadIdx.x;
    const int cl  = tid >> 4;
    const int n   = tid & 15;
    const int ch  = blockIdx.x * 16 + cl;
    const int b   = ch >> 9, d = ch & (DIN - 1);
    const int chunk = blockIdx.y;
    const int l0  = chunk * CL;

    const float Aval = -expf(A_log[d * NSS + n]);
    const float* dtp = dtT + (size_t)ch * LL + l0;
    const float* xcp = xcT + (size_t)ch * LL + l0;
    const float* xrow = xdbl + ((size_t)(b * LL + l0)) * 64;

    auto fill = [&](int tile, int s) {
        const int r = tid >> 2, c = tid & 3;
        cp16(smem_u32(&bufB[s][r][c * 4]), xrow + ((size_t)(tile * 64 + r)) * 64 + 16 + c * 4);
    };
    fill(0, 0); CP_COMMIT();
    fill(1, 1); CP_COMMIT();

    float h = 0.f, Pp = 1.f;
    #pragma unroll
    for (int tile = 0; tile < CL / 64; tile++) {
        if (tile == 0) asm volatile("cp.async.wait_group 1;" ::: "memory");
        else           asm volatile("cp.async.wait_group 0;" ::: "memory");
        __syncthreads();
        const int s = tile & 1;
        const float* dtb_ = dtp + tile * 64;
        const float* xcb_ = xcp + tile * 64;
        #pragma unroll 4
        for (int j4 = 0; j4 < 64; j4 += 4) {
            const float4 d4 = *(const float4*)(dtb_ + j4);
            const float4 x4 = *(const float4*)(xcb_ + j4);
            const float dts[4] = {d4.x, d4.y, d4.z, d4.w};
            const float xcs[4] = {x4.x, x4.y, x4.z, x4.w};
            #pragma unroll
            for (int u = 0; u < 4; u++) {
                const float dtv = dts[u];
                const float xv  = xcs[u];
                const float Bv  = bufB[s][j4 + u][n];
                const float dA  = __expf(dtv * Aval);
                h = fmaf(dA, h, dtv * Bv * xv);
                Pp *= dA;
            }
        }
        __syncthreads();
    }
    const int idx = (ch * GCH + chunk) * NSS + n;
    Pst[idx] = Pp;
    He[idx]  = h;
}

// pass3: inline combine, scan + gate, SMEM-staged coalesced output stores.
__global__ __launch_bounds__(256)
void scan_p3(const float* __restrict__ dtT, const float* __restrict__ xdbl,
             const float* __restrict__ xcT, const float* __restrict__ zsT,
             const float* __restrict__ A_log, const float* __restrict__ D_ssm,
             const float* __restrict__ Pst, const float* __restrict__ He,
             __nv_bfloat16* __restrict__ yg)
{
    __shared__ __align__(16) float buf[2][64][32];
    __shared__ __align__(16) __nv_bfloat16 sy[64][16];   // staged y for one 64-step tile
    const int tid  = threadIdx.x;
    const int lane = tid & 31;
    const int n    = lane & 15;
    const int hw   = lane >> 4;
    const int w    = tid >> 5;
    const int cl   = w * 2 + hw;                         // local channel 0..15
    const int ch   = blockIdx.x * 16 + cl;
    const int b    = ch >> 9, d0 = (blockIdx.x * 16) & (DIN - 1);
    const int d    = ch & (DIN - 1);
    const int chunk = blockIdx.y;
    const int l0   = chunk * CL;

    const float Aval = -expf(A_log[d * NSS + n]);
    const float Dv   = D_ssm[d];
    const float* dtp = dtT + (size_t)ch * LL + l0;
    const float* xcp = xcT + (size_t)ch * LL + l0;
    const float* zp  = zsT + (size_t)ch * LL + l0;
    const float* xrow = xdbl + ((size_t)(b * LL + l0)) * 64;

    auto fill = [&](int tile, int s) {
        #pragma unroll
        for (int i = 0; i < 2; i++) {
            const int idx = i * 256 + tid;
            const int r = idx >> 3, c = idx & 7;
            cp16(smem_u32(&buf[s][r][c * 4]), xrow + ((size_t)(tile * 64 + r)) * 64 + 16 + c * 4);
        }
    };
    fill(0, 0); CP_COMMIT();
    fill(1, 1); CP_COMMIT();

    // inline combine (folded scan_p2)
    float h = 0.f;
    for (int c = 0; c < chunk; c++) {
        const int idx = (ch * GCH + c) * NSS + n;
        h = fmaf(Pst[idx], h, He[idx]);
    }

    #pragma unroll
    for (int tile = 0; tile < CL / 64; tile++) {
        if (tile == 0) asm volatile("cp.async.wait_group 1;" ::: "memory");
        else           asm volatile("cp.async.wait_group 0;" ::: "memory");
        __syncthreads();                                   // buf ready (also guards sy reuse)
        const int s = tile & 1;
        const float* dtb_ = dtp + tile * 64;
        const float* xcb_ = xcp + tile * 64;
        const float* zb_  = zp  + tile * 64;
        #pragma unroll 2
        for (int j4 = 0; j4 < 64; j4 += 4) {
            const float4 d4 = *(const float4*)(dtb_ + j4);
            const float4 x4 = *(const float4*)(xcb_ + j4);
            const float4 z4 = *(const float4*)(zb_ + j4);
            const float dts[4] = {d4.x, d4.y, d4.z, d4.w};
            const float xcs[4] = {x4.x, x4.y, x4.z, x4.w};
            const float zs[4]  = {z4.x, z4.y, z4.z, z4.w};
            #pragma unroll
            for (int u = 0; u < 4; u++) {
                const int j = j4 + u;
                const float dtv = dts[u];
                const float xv  = xcs[u];
                const float Bv  = buf[s][j][n];
                const float Cv  = buf[s][j][16 + n];
                const float dA  = __expf(dtv * Aval);
                h = fmaf(dA, h, dtv * Bv * xv);
                float p = h * Cv;
                p += __shfl_xor_sync(0xffffffffu, p, 8);
                p += __shfl_xor_sync(0xffffffffu, p, 4);
                p += __shfl_xor_sync(0xffffffffu, p, 2);
                p += __shfl_xor_sync(0xffffffffu, p, 1);
                if (n == 0) {
                    const float y = p + xv * Dv;
                    sy[j][cl] = __float2bfloat16(y * zs[u]);
                }
            }
        }
        __syncthreads();                                   // sy complete
        // cooperative coalesced store: 128 threads x 16B (8 bf16 each)
        if (tid < 128) {
            const int j = tid >> 1, half = tid & 1;
            const size_t o = ((size_t)(b * LL + l0 + tile * 64 + j)) * DIN + d0 + half * 8;
            *(uint4*)(yg + o) = *(const uint4*)(&sy[j][half * 8]);
        }
    }
}

// ---------------- warp-per-row residual-add + LayerNorm (8 rows/block) ----------------
__global__ __launch_bounds__(256)
void ln_add_kernel(const float* __restrict__ a, const float* __restrict__ badd,
                   const float* __restrict__ g, const float* __restrict__ beta,
                   float* __restrict__ out, __nv_bfloat16* __restrict__ outb)
{
    const int row  = blockIdx.x * 8 + (threadIdx.x >> 5);
    const int lane = threadIdx.x & 31;
    const float* ar = a    + (size_t)row * DD;
    const float* br = badd + (size_t)row * DD;

    float4 va0 = *(const float4*)(ar + lane * 4);
    float4 vb0 = *(const float4*)(br + lane * 4);
    float4 va1 = *(const float4*)(ar + 128 + lane * 4);
    float4 vb1 = *(const float4*)(br + 128 + lane * 4);
    float v[8] = { va0.x + vb0.x, va0.y + vb0.y, va0.z + vb0.z, va0.w + vb0.w,
                   va1.x + vb1.x, va1.y + vb1.y, va1.z + vb1.z, va1.w + vb1.w };
    float s = 0.f, s2 = 0.f;
    #pragma unroll
    for (int i = 0; i < 8; i++) { s += v[i]; s2 += v[i] * v[i]; }
    #pragma unroll
    for (int m = 16; m > 0; m >>= 1) {
        s  += __shfl_xor_sync(0xffffffffu, s,  m);
        s2 += __shfl_xor_sync(0xffffffffu, s2, m);
    }
    const float mean = s * (1.f / DD);
    const float var  = s2 * (1.f / DD) - mean * mean;
    const float inv  = rsqrtf(var + 1e-5f);

    const float4 g0 = *(const float4*)(g + lane * 4);
    const float4 g1 = *(const float4*)(g + 128 + lane * 4);
    const float4 e0 = *(const float4*)(beta + lane * 4);
    const float4 e1 = *(const float4*)(beta + 128 + lane * 4);
    float o[8];
    o[0] = (v[0]-mean)*inv*g0.x + e0.x;  o[1] = (v[1]-mean)*inv*g0.y + e0.y;
    o[2] = (v[2]-mean)*inv*g0.z + e0.z;  o[3] = (v[3]-mean)*inv*g0.w + e0.w;
    o[4] = (v[4]-mean)*inv*g1.x + e1.x;  o[5] = (v[5]-mean)*inv*g1.y + e1.y;
    o[6] = (v[6]-mean)*inv*g1.z + e1.z;  o[7] = (v[7]-mean)*inv*g1.w + e1.w;

    float* orow = out + (size_t)row * DD;
    *(float4*)(orow + lane * 4)       = make_float4(o[0], o[1], o[2], o[3]);
    *(float4*)(orow + 128 + lane * 4) = make_float4(o[4], o[5], o[6], o[7]);
    if (outb) {
        __nv_bfloat16* brow = outb + (size_t)row * DD;
        *(__nv_bfloat162*)(brow + lane * 4)           = __float22bfloat162_rn(make_float2(o[0], o[1]));
        *(__nv_bfloat162*)(brow + lane * 4 + 2)       = __float22bfloat162_rn(make_float2(o[2], o[3]));
        *(__nv_bfloat162*)(brow + 128 + lane * 4)     = __float22bfloat162_rn(make_float2(o[4], o[5]));
        *(__nv_bfloat162*)(brow + 128 + lane * 4 + 2) = __float22bfloat162_rn(make_float2(o[6], o[7]));
    }
}

// ---------------- launch ----------------
extern "C" void kernel_launch(void* const* d_in, const int* in_sizes, int n_in,
                              void* d_out, int out_size)
{
    const float* x          = (const float*)d_in[0];
    const float* in_proj_w  = (const float*)d_in[1];
    const float* in_proj_b  = (const float*)d_in[2];
    const float* conv_w     = (const float*)d_in[3];
    const float* conv_b     = (const float*)d_in[4];
    const float* x_proj_w   = (const float*)d_in[5];
    const float* dt_proj_w  = (const float*)d_in[6];
    const float* dt_proj_b  = (const float*)d_in[7];
    const float* A_log      = (const float*)d_in[8];
    const float* D_ssm      = (const float*)d_in[9];
    const float* out_proj_w = (const float*)d_in[10];
    const float* out_proj_b = (const float*)d_in[11];
    const float* ln1_g      = (const float*)d_in[12];
    const float* ln1_b      = (const float*)d_in[13];
    const float* fc1_w      = (const float*)d_in[14];
    const float* fc1_b      = (const float*)d_in[15];
    const float* fc2_w      = (const float*)d_in[16];
    const float* fc2_b      = (const float*)d_in[17];
    const float* ln2_g      = (const float*)d_in[18];
    const float* ln2_b      = (const float*)d_in[19];
    float* out = (float*)d_out;

    float *xz, *xcT, *zsT, *xdbl, *dtT, *Pst, *He, *ssm, *y1, *f2, *zero;
    __nv_bfloat16 *xconvb, *ygb, *y1b, *h1b, *xb, *w_in, *w_xp, *w_out, *w_fc1, *w_fc2;
    cudaGetSymbolAddress((void**)&xz,     g_xz);
    cudaGetSymbolAddress((void**)&xcT,    g_xcT);
    cudaGetSymbolAddress((void**)&zsT,    g_zsT);
    cudaGetSymbolAddress((void**)&xconvb, g_xconvb);
    cudaGetSymbolAddress((void**)&xdbl,   g_xdbl);
    cudaGetSymbolAddress((void**)&dtT,    g_dtT);
    cudaGetSymbolAddress((void**)&Pst,    g_P);
    cudaGetSymbolAddress((void**)&He,     g_He);
    cudaGetSymbolAddress((void**)&ygb,    g_ygb);
    cudaGetSymbolAddress((void**)&ssm,    g_ssm);
    cudaGetSymbolAddress((void**)&y1,     g_y1);
    cudaGetSymbolAddress((void**)&y1b,    g_y1b);
    cudaGetSymbolAddress((void**)&h1b,    g_h1b);
    cudaGetSymbolAddress((void**)&f2,     g_f2);
    cudaGetSymbolAddress((void**)&xb,     g_xb);
    cudaGetSymbolAddress((void**)&w_in,   g_w_in);
    cudaGetSymbolAddress((void**)&w_xp,   g_w_xp);
    cudaGetSymbolAddress((void**)&w_out,  g_w_out);
    cudaGetSymbolAddress((void**)&w_fc1,  g_w_fc1);
    cudaGetSymbolAddress((void**)&w_fc2,  g_w_fc2);
    cudaGetSymbolAddress((void**)&zero,   g_zero);

    const int SM128_128 = 3 * (128 + 128) * 72 * 2;  // 110592
    const int SM64_64   = 3 * (64  + 64)  * 72 * 2;  // 55296
    const int SM64_128  = 3 * (64  + 128) * 72 * 2;  // 82944
    cudaFuncSetAttribute(mma_gemm<128,128,0,0>, cudaFuncAttributeMaxDynamicSharedMemorySize, SM128_128);
    cudaFuncSetAttribute(mma_gemm<128,128,1,1>, cudaFuncAttributeMaxDynamicSharedMemorySize, SM128_128);
    cudaFuncSetAttribute(mma_gemm<64,128,1,0>,  cudaFuncAttributeMaxDynamicSharedMemorySize, SM64_128);
    cudaFuncSetAttribute(mma_gemm<64,128,0,0>,  cudaFuncAttributeMaxDynamicSharedMemorySize, SM64_128);
    cudaFuncSetAttribute(mma_gemm<64,64,0,0>,   cudaFuncAttributeMaxDynamicSharedMemorySize, SM64_64);

    // 1) all conversions
    cvt_all_kernel<<<(CV0+CV1+CV2+CV3+CV4+CV5 + 255)/256, 256>>>(
        x, xb, in_proj_w, w_in, out_proj_w, w_out, fc1_w, w_fc1, fc2_w, w_fc2, x_proj_w, w_xp);
    // 2) in_proj GEMM -> xz fp32
    mma_gemm<128,128,0,0><<<dim3(2*DIN/128, TOK/128), 256, SM128_128>>>(xb, w_in, in_proj_b, xz, 2*DIN, DD);
    // 3) conv + silu + transpose
    conv_silu_tr<<<dim3(LL/32, DIN/64, BB), 256>>>(xz, conv_w, conv_b, xconvb, xcT, zsT);
    // 4) x_proj GEMM -> xdbl (BM=64)
    mma_gemm<64,64,0,0><<<dim3(1, TOK/64), 256, SM64_64>>>(xconvb, w_xp, zero, xdbl, 64, DIN);
    // 5) dt_proj + softplus -> dtT channel-major
    gemm_kernel_sp<<<dim3(DIN/128, TOK/128), 256>>>(xdbl, 64, dt_proj_w, dt_proj_b, dtT, DIN, DTR_);
    // 6-7) chunked parallel scan
    scan_p1<<<dim3(NCH/16, GCH), 256>>>(dtT, xdbl, xcT, A_log, Pst, He);
    scan_p3<<<dim3(NCH/16, GCH), 256>>>(dtT, xdbl, xcT, zsT, A_log, D_ssm, Pst, He, ygb);
    // 8) out_proj GEMM -> ssm (BM=64)
    mma_gemm<64,128,0,0><<<dim3(DD/128, TOK/64), 256, SM64_128>>>(ygb, w_out, out_proj_b, ssm, DD, DIN);
    // 9) LN1(x + ssm)
    ln_add_kernel<<<TOK/8, 256>>>(x, ssm, ln1_g, ln1_b, y1, y1b);
    // 10) fc1 + gelu
    mma_gemm<128,128,1,1><<<dim3(DFF_/128, TOK/128), 256, SM128_128>>>(y1b, w_fc1, fc1_b, h1b, DFF_, DD);
    // 11) fc2 + gelu (BM=64)
    mma_gemm<64,128,1,0><<<dim3(DD/128, TOK/64), 256, SM64_128>>>(h1b, w_fc2, fc2_b, f2, DD, DFF_);
    // 12) LN2(y1 + ffn) -> out
    ln_add_kernel<<<TOK/8, 256>>>(y1, f2, ln2_g, ln2_b, out, (__nv_bfloat16*)0);
}

// round 16
// speedup vs baseline: 1.0544x; 1.0544x over previous
#include <cuda_runtime.h>
#include <cuda_bf16.h>
#include <math.h>
#include <stdint.h>

// Problem constants (fixed shapes)
#define BB   4
#define LL   2048
#define DD   256
#define DIN  512
#define NSS  16
#define DTR_ 16
#define DFF_ 1024
#define TOK  (BB*LL)      // 8192
#define NCH  (BB*DIN)     // 2048 scan channels
#define GCH  16           // scan chunks
#define CL   (LL/GCH)     // 128 steps per chunk

// ---------------- scratch (static device memory) ----------------
__device__ float          g_xz    [TOK * 2 * DIN];
__device__ float          g_xcT   [TOK * DIN];
__device__ float          g_zsT   [TOK * DIN];
__device__ __nv_bfloat16  g_xconvb[TOK * DIN];
__device__ float          g_xdbl  [TOK * 64];
__device__ float          g_dtT   [TOK * DIN];
__device__ float          g_P     [NCH * GCH * NSS];
__device__ float          g_He    [NCH * GCH * NSS];
__device__ __nv_bfloat16  g_ygb   [TOK * DIN];
__device__ float          g_ssm   [TOK * DD];
__device__ float          g_y1    [TOK * DD];
__device__ __nv_bfloat16  g_y1b   [TOK * DD];
__device__ __nv_bfloat16  g_h1b   [TOK * DFF_];
__device__ float          g_f2    [TOK * DD];
__device__ __nv_bfloat16  g_xb    [TOK * DD];
__device__ __nv_bfloat16  g_w_in  [2 * DIN * DD];
__device__ __nv_bfloat16  g_w_xp  [64 * DIN];
__device__ __nv_bfloat16  g_w_out [DD * DIN];
__device__ __nv_bfloat16  g_w_fc1 [DFF_ * DD];
__device__ __nv_bfloat16  g_w_fc2 [DD * DFF_];
__device__ float          g_zero  [64];

// ---------------- math helpers ----------------
__device__ __forceinline__ float siluf(float v)     { return v / (1.f + __expf(-v)); }
__device__ __forceinline__ float geluf(float v)     { return 0.5f * v * (1.f + erff(v * 0.70710678118654752f)); }
__device__ __forceinline__ float softplusf(float v) { return fmaxf(v, 0.f) + log1pf(__expf(-fabsf(v))); }

__device__ __forceinline__ uint32_t smem_u32(const void* p) {
    uint32_t a;
    asm("{ .reg .u64 t; cvta.to.shared.u64 t, %1; cvt.u32.u64 %0, t; }" : "=r"(a) : "l"(p));
    return a;
}
__device__ __forceinline__ void ldsm4(uint32_t& r0, uint32_t& r1, uint32_t& r2, uint32_t& r3, uint32_t addr) {
    asm volatile("ldmatrix.sync.aligned.m8n8.x4.shared.b16 {%0,%1,%2,%3}, [%4];"
                 : "=r"(r0), "=r"(r1), "=r"(r2), "=r"(r3) : "r"(addr));
}
__device__ __forceinline__ void mma16816(float* c, const uint32_t* a, const uint32_t* b) {
    asm volatile("mma.sync.aligned.m16n8k16.row.col.f32.bf16.bf16.f32 "
                 "{%0,%1,%2,%3},{%4,%5,%6,%7},{%8,%9},{%0,%1,%2,%3};"
                 : "+f"(c[0]), "+f"(c[1]), "+f"(c[2]), "+f"(c[3])
                 : "r"(a[0]), "r"(a[1]), "r"(a[2]), "r"(a[3]), "r"(b[0]), "r"(b[1]));
}
__device__ __forceinline__ void cp16(uint32_t dst, const void* src) {
    asm volatile("cp.async.cg.shared.global [%0], [%1], 16;" :: "r"(dst), "l"(src));
}
#define CP_COMMIT() asm volatile("cp.async.commit_group;" ::: "memory")

// =======================================================================
// bf16 GEMM, BM templated (128 or 64). BK=64, 3-stage cp.async, one
// __syncthreads per iteration. 256 threads = 2(M) x 4(N) warps.
// =======================================================================
template<int BMt, int BN, int EPI, int OUTT>
__global__ __launch_bounds__(256)
void mma_gemm(const __nv_bfloat16* __restrict__ A, const __nv_bfloat16* __restrict__ W,
              const float* __restrict__ bias, void* __restrict__ C, int N, int K)
{
    constexpr int BK  = 64;
    constexpr int AST = 72;
    constexpr int MI  = BMt / 32;
    constexpr int NT  = BN / 32;
    constexpr int ASZ = BMt * AST;
    constexpr int BSZ = BN * AST;

    extern __shared__ __nv_bfloat16 smem[];
    __nv_bfloat16* sA = smem;
    __nv_bfloat16* sB = smem + 3 * ASZ;

    const int tid  = threadIdx.x;
    const int wid  = tid >> 5;
    const int lane = tid & 31;
    const int warp_m = wid & 1;
    const int warp_n = wid >> 1;
    const int rowBase = blockIdx.y * BMt;
    const int colBase = blockIdx.x * BN;
    const int NK = K >> 6;

    auto prefetch = [&](int s, int kc) {
        __nv_bfloat16* As = sA + s * ASZ;
        __nv_bfloat16* Bs = sB + s * BSZ;
        #pragma unroll
        for (int i = 0; i < BMt / 32; i++) {
            const int cidx = i * 256 + tid;
            const int row = cidx >> 3, c8 = cidx & 7;
            cp16(smem_u32(&As[row * AST + c8 * 8]),
                 A + (size_t)(rowBase + row) * K + kc * BK + c8 * 8);
        }
        #pragma unroll
        for (int i = 0; i < BN / 32; i++) {
            const int cidx = i * 256 + tid;
            const int row = cidx >> 3, c8 = cidx & 7;
            cp16(smem_u32(&Bs[row * AST + c8 * 8]),
                 W + (size_t)(colBase + row) * K + kc * BK + c8 * 8);
        }
    };

    float acc[MI][NT][4];
    #pragma unroll
    for (int mi = 0; mi < MI; mi++)
        #pragma unroll
        for (int ni = 0; ni < NT; ni++)
            #pragma unroll
            for (int r = 0; r < 4; r++) acc[mi][ni][r] = 0.f;

    prefetch(0, 0); CP_COMMIT();
    prefetch(1, 1); CP_COMMIT();

    for (int kt = 0; kt < NK; kt++) {
        if (kt + 1 < NK) asm volatile("cp.async.wait_group 1;" ::: "memory");
        else             asm volatile("cp.async.wait_group 0;" ::: "memory");
        __syncthreads();
        if (kt + 2 < NK) { prefetch((kt + 2) % 3, kt + 2); CP_COMMIT(); }

        const int s = kt % 3;
        __nv_bfloat16* As = sA + s * ASZ;
        __nv_bfloat16* Bs = sB + s * BSZ;
        #pragma unroll
        for (int k = 0; k < 4; k++) {
            uint32_t af[MI][4];
            #pragma unroll
            for (int mi = 0; mi < MI; mi++) {
                const int row = warp_m * (MI * 16) + mi * 16 + (lane & 15);
                const int col = k * 16 + (lane >> 4) * 8;
                ldsm4(af[mi][0], af[mi][1], af[mi][2], af[mi][3],
                      smem_u32(&As[row * AST + col]));
            }
            uint32_t bf[NT][2];
            #pragma unroll
            for (int np = 0; np < NT / 2; np++) {
                const int n0 = warp_n * (NT * 8) + np * 16;
                const int q  = lane >> 3;
                const int row = n0 + (q & 1) * 8 + (lane & 7);
                const int col = k * 16 + (q >> 1) * 8;
                uint32_t r0, r1, r2, r3;
                ldsm4(r0, r1, r2, r3, smem_u32(&Bs[row * AST + col]));
                bf[np*2][0] = r0; bf[np*2+1][0] = r1;
                bf[np*2][1] = r2; bf[np*2+1][1] = r3;
            }
            #pragma unroll
            for (int mi = 0; mi < MI; mi++)
                #pragma unroll
                for (int ni = 0; ni < NT; ni++)
                    mma16816(acc[mi][ni], af[mi], bf[ni]);
        }
    }
    __syncthreads();

    const int g  = lane >> 2;
    const int c2 = (lane & 3) * 2;
    #pragma unroll
    for (int mi = 0; mi < MI; mi++) {
        const int row0 = rowBase + warp_m * (MI * 16) + mi * 16 + g;
        #pragma unroll
        for (int ni = 0; ni < NT; ni++) {
            const int col = colBase + warp_n * (NT * 8) + ni * 8 + c2;
            const float b0 = bias[col], b1 = bias[col + 1];
            float v00 = acc[mi][ni][0] + b0, v01 = acc[mi][ni][1] + b1;
            float v10 = acc[mi][ni][2] + b0, v11 = acc[mi][ni][3] + b1;
            if (EPI == 1) { v00 = geluf(v00); v01 = geluf(v01); v10 = geluf(v10); v11 = geluf(v11); }
            if (OUTT == 0) {
                *(float2*)((float*)C + (size_t)row0 * N + col)       = make_float2(v00, v01);
                *(float2*)((float*)C + (size_t)(row0 + 8) * N + col) = make_float2(v10, v11);
            } else {
                __nv_bfloat16* Cb = (__nv_bfloat16*)C;
                *(__nv_bfloat162*)(Cb + (size_t)row0 * N + col)       = __float22bfloat162_rn(make_float2(v00, v01));
                *(__nv_bfloat162*)(Cb + (size_t)(row0 + 8) * N + col) = __float22bfloat162_rn(make_float2(v10, v11));
            }
        }
    }
}

// ---------------- single fused converter (float4-vectorized) ----------------
#define CV0 (TOK*DD)
#define CV1 (2*DIN*DD)
#define CV2 (DD*DIN)
#define CV3 (DFF_*DD)
#define CV4 (DD*DFF_)
#define CV5 (64*DIN)
__device__ __forceinline__ void cvt4(const float* __restrict__ src, __nv_bfloat16* __restrict__ dst, int i) {
    const float4 v = *(const float4*)(src + i);
    *(__nv_bfloat162*)(dst + i)     = __float22bfloat162_rn(make_float2(v.x, v.y));
    *(__nv_bfloat162*)(dst + i + 2) = __float22bfloat162_rn(make_float2(v.z, v.w));
}
__global__ void cvt_all_kernel(const float* __restrict__ x,        __nv_bfloat16* __restrict__ xb,
                               const float* __restrict__ w_in,     __nv_bfloat16* __restrict__ ob_in,
                               const float* __restrict__ w_out,    __nv_bfloat16* __restrict__ ob_out,
                               const float* __restrict__ w_fc1,    __nv_bfloat16* __restrict__ ob_fc1,
                               const float* __restrict__ w_fc2,    __nv_bfloat16* __restrict__ ob_fc2,
                               const float* __restrict__ w_xp,     __nv_bfloat16* __restrict__ ob_xp)
{
    int i = (blockIdx.x * blockDim.x + threadIdx.x) * 4;
    if (i < CV0) { cvt4(x, xb, i);         return; }  i -= CV0;
    if (i < CV1) { cvt4(w_in, ob_in, i);   return; }  i -= CV1;
    if (i < CV2) { cvt4(w_out, ob_out, i); return; }  i -= CV2;
    if (i < CV3) { cvt4(w_fc1, ob_fc1, i); return; }  i -= CV3;
    if (i < CV4) { cvt4(w_fc2, ob_fc2, i); return; }  i -= CV4;
    if (i < CV5) {
        const int r = i >> 9;  // 4 | 512 so all 4 elems share row r
        if (r < 48) cvt4(w_xp, ob_xp, i);  // layouts identical for r < 48
        else {
            const __nv_bfloat162 z = __float22bfloat162_rn(make_float2(0.f, 0.f));
            *(__nv_bfloat162*)(ob_xp + i)     = z;
            *(__nv_bfloat162*)(ob_xp + i + 2) = z;
        }
    }
}

// ---------------- SIMT SGEMM for dt_proj (K=16) -> dtT channel-major ----------------
__global__ __launch_bounds__(256)
void gemm_kernel_sp(const float* __restrict__ A, int lda,
                    const float* __restrict__ W, const float* __restrict__ bias,
                    float* __restrict__ dtT, int N, int K)
{
    __shared__ float As[16][132];
    __shared__ float Bs[16][132];
    const int tid = threadIdx.x;
    const int tx = tid & 15, ty = tid >> 4;
    const int rowBase = blockIdx.y * 128, colBase = blockIdx.x * 128;
    const int r = tid >> 2, c4 = tid & 3;
    float acc[8][8];
    #pragma unroll
    for (int i = 0; i < 8; i++) {
        #pragma unroll
        for (int j = 0; j < 8; j++) acc[i][j] = 0.f;
    }
    for (int kt = 0; kt < K; kt += 16) {
        #pragma unroll
        for (int rr = r; rr < 128; rr += 64) {
            float4 va = *reinterpret_cast<const float4*>(&A[(size_t)(rowBase + rr) * lda + kt + c4 * 4]);
            As[c4*4+0][rr] = va.x; As[c4*4+1][rr] = va.y; As[c4*4+2][rr] = va.z; As[c4*4+3][rr] = va.w;
            float4 vb = *reinterpret_cast<const float4*>(&W[(size_t)(colBase + rr) * K + kt + c4 * 4]);
            Bs[c4*4+0][rr] = vb.x; Bs[c4*4+1][rr] = vb.y; Bs[c4*4+2][rr] = vb.z; Bs[c4*4+3][rr] = vb.w;
        }
        __syncthreads();
        #pragma unroll
        for (int k = 0; k < 16; k++) {
            float a8[8], b8[8];
            #pragma unroll
            for (int i = 0; i < 8; i++) a8[i] = As[k][ty * 8 + i];
            #pragma unroll
            for (int j = 0; j < 8; j++) b8[j] = Bs[k][tx * 8 + j];
            #pragma unroll
            for (int i = 0; i < 8; i++)
                #pragma unroll
                for (int j = 0; j < 8; j++) acc[i][j] = fmaf(a8[i], b8[j], acc[i][j]);
        }
        __syncthreads();
    }
    const int t0 = rowBase + ty * 8;
    const int b  = t0 >> 11;
    const int l  = t0 & 2047;
    #pragma unroll
    for (int j = 0; j < 8; j++) {
        const int col = colBase + tx * 8 + j;
        const float bj = bias[col];
        float v[8];
        #pragma unroll
        for (int i = 0; i < 8; i++) v[i] = softplusf(acc[i][j] + bj);
        float* o = dtT + ((size_t)(b * DIN + col)) * LL + l;
        *(float4*)(o)     = make_float4(v[0], v[1], v[2], v[3]);
        *(float4*)(o + 4) = make_float4(v[4], v[5], v[6], v[7]);
    }
}

// ---------------- conv+silu with transpose: 64-channel tiles, float4 IO ----------------
__global__ __launch_bounds__(256)
void conv_silu_tr(const float* __restrict__ xz, const float* __restrict__ cw,
                  const float* __restrict__ cb, __nv_bfloat16* __restrict__ xconvb,
                  float* __restrict__ xcT, float* __restrict__ zsT)
{
    __shared__ float sxi[35][65];
    __shared__ float sout[32][65];
    __shared__ float sz[32][65];
    const int l0 = blockIdx.x * 32;
    const int d0 = blockIdx.y * 64;
    const int b  = blockIdx.z;
    const int tid = threadIdx.x;

    #pragma unroll 2
    for (int i = tid; i < 35 * 16; i += 256) {
        const int r = i >> 4, c4 = (i & 15) * 4;
        const int l = l0 - 3 + r;
        float4 v = make_float4(0.f, 0.f, 0.f, 0.f);
        if (l >= 0) v = *(const float4*)&xz[((size_t)(b * LL + l)) * (2 * DIN) + d0 + c4];
        sxi[r][c4+0] = v.x; sxi[r][c4+1] = v.y; sxi[r][c4+2] = v.z; sxi[r][c4+3] = v.w;
    }
    #pragma unroll 2
    for (int i = tid; i < 32 * 16; i += 256) {
        const int r = i >> 4, c4 = (i & 15) * 4;
        float4 v = *(const float4*)&xz[((size_t)(b * LL + l0 + r)) * (2 * DIN) + DIN + d0 + c4];
        sz[r][c4+0] = v.x; sz[r][c4+1] = v.y; sz[r][c4+2] = v.z; sz[r][c4+3] = v.w;
    }
    __syncthreads();
    #pragma unroll 4
    for (int i = tid; i < 32 * 64; i += 256) {
        const int l = i >> 6, c = i & 63;
        const int d = d0 + c;
        float v = cb[d] + cw[d*4+3] * sxi[l+3][c] + cw[d*4+2] * sxi[l+2][c]
                        + cw[d*4+1] * sxi[l+1][c] + cw[d*4+0] * sxi[l][c];
        v = siluf(v);
        sout[l][c] = v;
        xconvb[((size_t)(b * LL + l0 + l)) * DIN + d] = __float2bfloat16(v);
    }
    __syncthreads();
    #pragma unroll 2
    for (int i = tid; i < 64 * 8; i += 256) {
        const int c = i >> 3, lg = (i & 7) * 4;
        const size_t o = ((size_t)(b * DIN + d0 + c)) * LL + l0 + lg;
        *(float4*)&xcT[o] = make_float4(sout[lg][c], sout[lg+1][c], sout[lg+2][c], sout[lg+3][c]);
        *(float4*)&zsT[o] = make_float4(siluf(sz[lg][c]), siluf(sz[lg+1][c]),
                                        siluf(sz[lg+2][c]), siluf(sz[lg+3][c]));
    }
}

// ---------------- chunked parallel scan (float4-batched broadcast loads) ----------------
__global__ __launch_bounds__(256)
void scan_p1(const float* __restrict__ dtT, const float* __restrict__ xdbl,
             const float* __restrict__ xcT, const float* __restrict__ A_log,
             float* __restrict__ Pst, float* __restrict__ He)
{
    __shared__ __align__(16) float bufB[2][64][16];
    const int tid = threadIdx.x;
    const int cl  = tid >> 4;
    const int n   = tid & 15;
    const int ch  = blockIdx.x * 16 + cl;
    const int b   = ch >> 9, d = ch & (DIN - 1);
    const int chunk = blockIdx.y;
    const int l0  = chunk * CL;

    const float Aval = -expf(A_log[d * NSS + n]);
    const float* dtp = dtT + (size_t)ch * LL + l0;
    const float* xcp = xcT + (size_t)ch * LL + l0;
    const float* xrow = xdbl + ((size_t)(b * LL + l0)) * 64;

    auto fill = [&](int tile, int s) {
        const int r = tid >> 2, c = tid & 3;
        cp16(smem_u32(&bufB[s][r][c * 4]), xrow + ((size_t)(tile * 64 + r)) * 64 + 16 + c * 4);
    };
    fill(0, 0); CP_COMMIT();
    fill(1, 1); CP_COMMIT();

    float h = 0.f, Pp = 1.f;
    #pragma unroll
    for (int tile = 0; tile < CL / 64; tile++) {
        if (tile == 0) asm volatile("cp.async.wait_group 1;" ::: "memory");
        else           asm volatile("cp.async.wait_group 0;" ::: "memory");
        __syncthreads();
        const int s = tile & 1;
        const float* dtb_ = dtp + tile * 64;
        const float* xcb_ = xcp + tile * 64;
        #pragma unroll 4
        for (int j4 = 0; j4 < 64; j4 += 4) {
            const float4 d4 = *(const float4*)(dtb_ + j4);
            const float4 x4 = *(const float4*)(xcb_ + j4);
            const float dts[4] = {d4.x, d4.y, d4.z, d4.w};
            const float xcs[4] = {x4.x, x4.y, x4.z, x4.w};
            #pragma unroll
            for (int u = 0; u < 4; u++) {
                const float dtv = dts[u];
                const float xv  = xcs[u];
                const float Bv  = bufB[s][j4 + u][n];
                const float dA  = __expf(dtv * Aval);
                h = fmaf(dA, h, dtv * Bv * xv);
                Pp *= dA;
            }
        }
        __syncthreads();
    }
    const int idx = (ch * GCH + chunk) * NSS + n;
    Pst[idx] = Pp;
    He[idx]  = h;
}

// pass3 (round-14 version): inline combine, scan + gate, lane-0 direct stores.
__global__ __launch_bounds__(256)
void scan_p3(const float* __restrict__ dtT, const float* __restrict__ xdbl,
             const float* __restrict__ xcT, const float* __restrict__ zsT,
             const float* __restrict__ A_log, const float* __restrict__ D_ssm,
             const float* __restrict__ Pst, const float* __restrict__ He,
             __nv_bfloat16* __restrict__ yg)
{
    __shared__ __align__(16) float buf[2][64][32];
    const int tid  = threadIdx.x;
    const int lane = tid & 31;
    const int n    = lane & 15;
    const int hw   = lane >> 4;
    const int w    = tid >> 5;
    const int ch   = blockIdx.x * 16 + w * 2 + hw;
    const int b    = ch >> 9, d = ch & (DIN - 1);
    const int chunk = blockIdx.y;
    const int l0   = chunk * CL;

    const float Aval = -expf(A_log[d * NSS + n]);
    const float Dv   = D_ssm[d];
    const float* dtp = dtT + (size_t)ch * LL + l0;
    const float* xcp = xcT + (size_t)ch * LL + l0;
    const float* zp  = zsT + (size_t)ch * LL + l0;
    const float* xrow = xdbl + ((size_t)(b * LL + l0)) * 64;

    auto fill = [&](int tile, int s) {
        #pragma unroll
        for (int i = 0; i < 2; i++) {
            const int idx = i * 256 + tid;
            const int r = idx >> 3, c = idx & 7;
            cp16(smem_u32(&buf[s][r][c * 4]), xrow + ((size_t)(tile * 64 + r)) * 64 + 16 + c * 4);
        }
    };
    fill(0, 0); CP_COMMIT();
    fill(1, 1); CP_COMMIT();

    // inline combine (folded scan_p2)
    float h = 0.f;
    for (int c = 0; c < chunk; c++) {
        const int idx = (ch * GCH + c) * NSS + n;
        h = fmaf(Pst[idx], h, He[idx]);
    }

    #pragma unroll
    for (int tile = 0; tile < CL / 64; tile++) {
        if (tile == 0) asm volatile("cp.async.wait_group 1;" ::: "memory");
        else           asm volatile("cp.async.wait_group 0;" ::: "memory");
        __syncthreads();
        const int s = tile & 1;
        const float* dtb_ = dtp + tile * 64;
        const float* xcb_ = xcp + tile * 64;
        const float* zb_  = zp  + tile * 64;
        #pragma unroll 2
        for (int j4 = 0; j4 < 64; j4 += 4) {
            const float4 d4 = *(const float4*)(dtb_ + j4);
            const float4 x4 = *(const float4*)(xcb_ + j4);
            const float4 z4 = *(const float4*)(zb_ + j4);
            const float dts[4] = {d4.x, d4.y, d4.z, d4.w};
            const float xcs[4] = {x4.x, x4.y, x4.z, x4.w};
            const float zs[4]  = {z4.x, z4.y, z4.z, z4.w};
            #pragma unroll
            for (int u = 0; u < 4; u++) {
                const int j = j4 + u;
                const float dtv = dts[u];
                const float xv  = xcs[u];
                const float Bv  = buf[s][j][n];
                const float Cv  = buf[s][j][16 + n];
                const float dA  = __expf(dtv * Aval);
                h = fmaf(dA, h, dtv * Bv * xv);
                float p = h * Cv;
                p += __shfl_xor_sync(0xffffffffu, p, 8);
                p += __shfl_xor_sync(0xffffffffu, p, 4);
                p += __shfl_xor_sync(0xffffffffu, p, 2);
                p += __shfl_xor_sync(0xffffffffu, p, 1);
                if (n == 0) {
                    const float y = p + xv * Dv;
                    yg[((size_t)(b * LL + l0 + tile * 64 + j)) * DIN + d] = __float2bfloat16(y * zs[u]);
                }
            }
        }
        __syncthreads();
    }
}

// ---------------- warp-per-row residual-add + LayerNorm (8 rows/block) ----------------
__global__ __launch_bounds__(256)
void ln_add_kernel(const float* __restrict__ a, const float* __restrict__ badd,
                   const float* __restrict__ g, const float* __restrict__ beta,
                   float* __restrict__ out, __nv_bfloat16* __restrict__ outb)
{
    const int row  = blockIdx.x * 8 + (threadIdx.x >> 5);
    const int lane = threadIdx.x & 31;
    const float* ar = a    + (size_t)row * DD;
    const float* br = badd + (size_t)row * DD;

    float4 va0 = *(const float4*)(ar + lane * 4);
    float4 vb0 = *(const float4*)(br + lane * 4);
    float4 va1 = *(const float4*)(ar + 128 + lane * 4);
    float4 vb1 = *(const float4*)(br + 128 + lane * 4);
    float v[8] = { va0.x + vb0.x, va0.y + vb0.y, va0.z + vb0.z, va0.w + vb0.w,
                   va1.x + vb1.x, va1.y + vb1.y, va1.z + vb1.z, va1.w + vb1.w };
    float s = 0.f, s2 = 0.f;
    #pragma unroll
    for (int i = 0; i < 8; i++) { s += v[i]; s2 += v[i] * v[i]; }
    #pragma unroll
    for (int m = 16; m > 0; m >>= 1) {
        s  += __shfl_xor_sync(0xffffffffu, s,  m);
        s2 += __shfl_xor_sync(0xffffffffu, s2, m);
    }
    const float mean = s * (1.f / DD);
    const float var  = s2 * (1.f / DD) - mean * mean;
    const float inv  = rsqrtf(var + 1e-5f);

    const float4 g0 = *(const float4*)(g + lane * 4);
    const float4 g1 = *(const float4*)(g + 128 + lane * 4);
    const float4 e0 = *(const float4*)(beta + lane * 4);
    const float4 e1 = *(const float4*)(beta + 128 + lane * 4);
    float o[8];
    o[0] = (v[0]-mean)*inv*g0.x + e0.x;  o[1] = (v[1]-mean)*inv*g0.y + e0.y;
    o[2] = (v[2]-mean)*inv*g0.z + e0.z;  o[3] = (v[3]-mean)*inv*g0.w + e0.w;
    o[4] = (v[4]-mean)*inv*g1.x + e1.x;  o[5] = (v[5]-mean)*inv*g1.y + e1.y;
    o[6] = (v[6]-mean)*inv*g1.z + e1.z;  o[7] = (v[7]-mean)*inv*g1.w + e1.w;

    float* orow = out + (size_t)row * DD;
    *(float4*)(orow + lane * 4)       = make_float4(o[0], o[1], o[2], o[3]);
    *(float4*)(orow + 128 + lane * 4) = make_float4(o[4], o[5], o[6], o[7]);
    if (outb) {
        __nv_bfloat16* brow = outb + (size_t)row * DD;
        *(__nv_bfloat162*)(brow + lane * 4)           = __float22bfloat162_rn(make_float2(o[0], o[1]));
        *(__nv_bfloat162*)(brow + lane * 4 + 2)       = __float22bfloat162_rn(make_float2(o[2], o[3]));
        *(__nv_bfloat162*)(brow + 128 + lane * 4)     = __float22bfloat162_rn(make_float2(o[4], o[5]));
        *(__nv_bfloat162*)(brow + 128 + lane * 4 + 2) = __float22bfloat162_rn(make_float2(o[6], o[7]));
    }
}

// ---------------- launch ----------------
extern "C" void kernel_launch(void* const* d_in, const int* in_sizes, int n_in,
                              void* d_out, int out_size)
{
    const float* x          = (const float*)d_in[0];
    const float* in_proj_w  = (const float*)d_in[1];
    const float* in_proj_b  = (const float*)d_in[2];
    const float* conv_w     = (const float*)d_in[3];
    const float* conv_b     = (const float*)d_in[4];
    const float* x_proj_w   = (const float*)d_in[5];
    const float* dt_proj_w  = (const float*)d_in[6];
    const float* dt_proj_b  = (const float*)d_in[7];
    const float* A_log      = (const float*)d_in[8];
    const float* D_ssm      = (const float*)d_in[9];
    const float* out_proj_w = (const float*)d_in[10];
    const float* out_proj_b = (const float*)d_in[11];
    const float* ln1_g      = (const float*)d_in[12];
    const float* ln1_b      = (const float*)d_in[13];
    const float* fc1_w      = (const float*)d_in[14];
    const float* fc1_b      = (const float*)d_in[15];
    const float* fc2_w      = (const float*)d_in[16];
    const float* fc2_b      = (const float*)d_in[17];
    const float* ln2_g      = (const float*)d_in[18];
    const float* ln2_b      = (const float*)d_in[19];
    float* out = (float*)d_out;

    float *xz, *xcT, *zsT, *xdbl, *dtT, *Pst, *He, *ssm, *y1, *f2, *zero;
    __nv_bfloat16 *xconvb, *ygb, *y1b, *h1b, *xb, *w_in, *w_xp, *w_out, *w_fc1, *w_fc2;
    cudaGetSymbolAddress((void**)&xz,     g_xz);
    cudaGetSymbolAddress((void**)&xcT,    g_xcT);
    cudaGetSymbolAddress((void**)&zsT,    g_zsT);
    cudaGetSymbolAddress((void**)&xconvb, g_xconvb);
    cudaGetSymbolAddress((void**)&xdbl,   g_xdbl);
    cudaGetSymbolAddress((void**)&dtT,    g_dtT);
    cudaGetSymbolAddress((void**)&Pst,    g_P);
    cudaGetSymbolAddress((void**)&He,     g_He);
    cudaGetSymbolAddress((void**)&ygb,    g_ygb);
    cudaGetSymbolAddress((void**)&ssm,    g_ssm);
    cudaGetSymbolAddress((void**)&y1,     g_y1);
    cudaGetSymbolAddress((void**)&y1b,    g_y1b);
    cudaGetSymbolAddress((void**)&h1b,    g_h1b);
    cudaGetSymbolAddress((void**)&f2,     g_f2);
    cudaGetSymbolAddress((void**)&xb,     g_xb);
    cudaGetSymbolAddress((void**)&w_in,   g_w_in);
    cudaGetSymbolAddress((void**)&w_xp,   g_w_xp);
    cudaGetSymbolAddress((void**)&w_out,  g_w_out);
    cudaGetSymbolAddress((void**)&w_fc1,  g_w_fc1);
    cudaGetSymbolAddress((void**)&w_fc2,  g_w_fc2);
    cudaGetSymbolAddress((void**)&zero,   g_zero);

    const int SM128_128 = 3 * (128 + 128) * 72 * 2;  // 110592
    const int SM64_64   = 3 * (64  + 64)  * 72 * 2;  // 55296
    const int SM64_128  = 3 * (64  + 128) * 72 * 2;  // 82944
    cudaFuncSetAttribute(mma_gemm<128,128,0,0>, cudaFuncAttributeMaxDynamicSharedMemorySize, SM128_128);
    cudaFuncSetAttribute(mma_gemm<128,128,1,1>, cudaFuncAttributeMaxDynamicSharedMemorySize, SM128_128);
    cudaFuncSetAttribute(mma_gemm<64,128,1,0>,  cudaFuncAttributeMaxDynamicSharedMemorySize, SM64_128);
    cudaFuncSetAttribute(mma_gemm<64,128,0,0>,  cudaFuncAttributeMaxDynamicSharedMemorySize, SM64_128);
    cudaFuncSetAttribute(mma_gemm<64,64,0,0>,   cudaFuncAttributeMaxDynamicSharedMemorySize, SM64_64);

    // 1) all conversions (float4)
    cvt_all_kernel<<<((CV0+CV1+CV2+CV3+CV4+CV5)/4 + 255)/256, 256>>>(
        x, xb, in_proj_w, w_in, out_proj_w, w_out, fc1_w, w_fc1, fc2_w, w_fc2, x_proj_w, w_xp);
    // 2) in_proj GEMM -> xz fp32
    mma_gemm<128,128,0,0><<<dim3(2*DIN/128, TOK/128), 256, SM128_128>>>(xb, w_in, in_proj_b, xz, 2*DIN, DD);
    // 3) conv + silu + transpose
    conv_silu_tr<<<dim3(LL/32, DIN/64, BB), 256>>>(xz, conv_w, conv_b, xconvb, xcT, zsT);
    // 4) x_proj GEMM -> xdbl (BM=64)
    mma_gemm<64,64,0,0><<<dim3(1, TOK/64), 256, SM64_64>>>(xconvb, w_xp, zero, xdbl, 64, DIN);
    // 5) dt_proj + softplus -> dtT channel-major
    gemm_kernel_sp<<<dim3(DIN/128, TOK/128), 256>>>(xdbl, 64, dt_proj_w, dt_proj_b, dtT, DIN, DTR_);
    // 6-7) chunked parallel scan
    scan_p1<<<dim3(NCH/16, GCH), 256>>>(dtT, xdbl, xcT, A_log, Pst, He);
    scan_p3<<<dim3(NCH/16, GCH), 256>>>(dtT, xdbl, xcT, zsT, A_log, D_ssm, Pst, He, ygb);
    // 8) out_proj GEMM -> ssm (BM=64)
    mma_gemm<64,128,0,0><<<dim3(DD/128, TOK/64), 256, SM64_128>>>(ygb, w_out, out_proj_b, ssm, DD, DIN);
    // 9) LN1(x + ssm)
    ln_add_kernel<<<TOK/8, 256>>>(x, ssm, ln1_g, ln1_b, y1, y1b);
    // 10) fc1 + gelu
    mma_gemm<128,128,1,1><<<dim3(DFF_/128, TOK/128), 256, SM128_128>>>(y1b, w_fc1, fc1_b, h1b, DFF_, DD);
    // 11) fc2 + gelu (BM=64)
    mma_gemm<64,128,1,0><<<dim3(DD/128, TOK/64), 256, SM64_128>>>(h1b, w_fc2, fc2_b, f2, DD, DFF_);
    // 12) LN2(y1 + ffn) -> out
    ln_add_kernel<<<TOK/8, 256>>>(y1, f2, ln2_g, ln2_b, out, (__nv_bfloat16*)0);
}